// round 1
// baseline (speedup 1.0000x reference)
#include <cuda_runtime.h>
#include <cstdint>
#include <cstddef>

#define B_    2
#define N_    2048
#define DIM_  1024
#define H_    16
#define DH_   64
#define MM_   16
#define J_    2064          // N_ + MM_
#define KTOP_ 64
#define SCALE_ 0.125f

// ---------------- static device scratch (no allocations allowed) ----------------
__device__ float g_cq  [(size_t)B_*N_*DIM_];        // x@Wq, (4096,1024)
__device__ float g_ckv [(size_t)B_*N_*2*DIM_];      // x@Wkv, (4096,2048)
__device__ float g_q   [(size_t)B_*H_*N_*DH_];      // (b,h,i,d)
__device__ float g_k   [(size_t)B_*H_*J_*DH_];      // (b,h,j,d), j<M = mem
__device__ float g_v   [(size_t)B_*H_*J_*DH_];
__device__ float g_smix[(size_t)B_*H_*N_*J_];       // mixed scores (b,k,i,j), 541MB
__device__ float g_att [(size_t)B_*N_*DIM_];        // attention output (b,i,k*64+d)

// ---------------- generic fp32 GEMM: 64x64 tile, BK=16, 256 thr, 4x4 micro ------
__device__ __forceinline__ void gemm_body(const float* __restrict__ A,
                                          const float* __restrict__ Bm,
                                          const float* __restrict__ bias,
                                          float* __restrict__ C,
                                          int Ndim, int Kdim)
{
    __shared__ __align__(16) float As[16][68];   // transposed A tile: As[k][m]
    __shared__ __align__(16) float Bs[16][68];   // Bs[k][n]

    const int tid = threadIdx.x;
    const int tx  = tid & 15;        // n micro
    const int ty  = tid >> 4;        // m micro
    const int m0  = blockIdx.y * 64;
    const int n0  = blockIdx.x * 64;

    const int lm = tid >> 2;           // 0..63  A row
    const int lk = (tid & 3) << 2;     // 0,4,8,12
    const int bk = tid >> 4;           // 0..15  B row
    const int bn = (tid & 15) << 2;    // 0..60

    float acc[4][4];
#pragma unroll
    for (int r = 0; r < 4; r++)
#pragma unroll
        for (int c = 0; c < 4; c++) acc[r][c] = 0.f;

    for (int k0 = 0; k0 < Kdim; k0 += 16) {
        float4 a = *(const float4*)(A + (size_t)(m0 + lm) * Kdim + k0 + lk);
        As[lk + 0][lm] = a.x; As[lk + 1][lm] = a.y;
        As[lk + 2][lm] = a.z; As[lk + 3][lm] = a.w;
        float4 b = *(const float4*)(Bm + (size_t)(k0 + bk) * Ndim + n0 + bn);
        *(float4*)&Bs[bk][bn] = b;
        __syncthreads();
#pragma unroll
        for (int k = 0; k < 16; k++) {
            const float4 av = *(const float4*)&As[k][ty << 2];
            const float4 bv = *(const float4*)&Bs[k][tx << 2];
            acc[0][0] += av.x * bv.x; acc[0][1] += av.x * bv.y;
            acc[0][2] += av.x * bv.z; acc[0][3] += av.x * bv.w;
            acc[1][0] += av.y * bv.x; acc[1][1] += av.y * bv.y;
            acc[1][2] += av.y * bv.z; acc[1][3] += av.y * bv.w;
            acc[2][0] += av.z * bv.x; acc[2][1] += av.z * bv.y;
            acc[2][2] += av.z * bv.z; acc[2][3] += av.z * bv.w;
            acc[3][0] += av.w * bv.x; acc[3][1] += av.w * bv.y;
            acc[3][2] += av.w * bv.z; acc[3][3] += av.w * bv.w;
        }
        __syncthreads();
    }

    float4 bz = make_float4(0.f, 0.f, 0.f, 0.f);
    if (bias) bz = *(const float4*)(bias + n0 + (tx << 2));
#pragma unroll
    for (int r = 0; r < 4; r++) {
        const int m = m0 + (ty << 2) + r;
        float4 o;
        o.x = acc[r][0] + bz.x; o.y = acc[r][1] + bz.y;
        o.z = acc[r][2] + bz.z; o.w = acc[r][3] + bz.w;
        *(float4*)(C + (size_t)m * Ndim + n0 + (tx << 2)) = o;
    }
}

__global__ void __launch_bounds__(256) k_gemm_q (const float* x, const float* Wq)
{ gemm_body(x, Wq, nullptr, g_cq, DIM_, DIM_); }
__global__ void __launch_bounds__(256) k_gemm_kv(const float* x, const float* Wkv)
{ gemm_body(x, Wkv, nullptr, g_ckv, 2*DIM_, DIM_); }
__global__ void __launch_bounds__(256) k_gemm_o (const float* Wo, const float* bo, float* out)
{ gemm_body(g_att, Wo, bo, out, DIM_, DIM_); }

// ---------------- layout scatter kernels -----------------------------------------
__global__ void k_scatter_q()
{
    int idx = blockIdx.x * blockDim.x + threadIdx.x;      // B*N*DIM elems
    int col = idx & (DIM_ - 1);
    int row = idx >> 10;
    int b = row >> 11, i = row & (N_ - 1);
    int h = col >> 6,  d = col & 63;
    g_q[(((size_t)(b * H_ + h)) * N_ + i) * DH_ + d] = g_cq[idx];
}

__global__ void k_scatter_kv()
{
    int idx = blockIdx.x * blockDim.x + threadIdx.x;      // B*N*2*DIM elems
    int col = idx & (2 * DIM_ - 1);
    int row = idx >> 11;
    int b = row >> 11, i = row & (N_ - 1);
    float val = g_ckv[idx];
    if (col < DIM_) {
        int h = col >> 6, d = col & 63;
        g_k[(((size_t)(b * H_ + h)) * J_ + MM_ + i) * DH_ + d] = val;
    } else {
        int c = col - DIM_;
        int h = c >> 6, d = c & 63;
        g_v[(((size_t)(b * H_ + h)) * J_ + MM_ + i) * DH_ + d] = val;
    }
}

__global__ void k_fill_mem(const float* __restrict__ mk, const float* __restrict__ mv)
{
    int idx = blockIdx.x * blockDim.x + threadIdx.x;      // B*H*M*DH elems
    int d = idx & 63;
    int r = idx >> 6;
    int j  = r % MM_;  r /= MM_;
    int h  = r % H_;
    int b  = r / H_;
    size_t dst = (((size_t)(b * H_ + h)) * J_ + j) * DH_ + d;
    size_t src = ((size_t)h * MM_ + j) * DH_ + d;
    g_k[dst] = mk[src];
    g_v[dst] = mv[src];
}

// ---------------- fused QK^T + head-mix (pre_proj) -------------------------------
// 32(i) x 32(j) tile, all 16 heads accumulated with mixing into 16 output heads.
__global__ void __launch_bounds__(256) k_dots_mix(const float* __restrict__ pre)
{
    const int b  = blockIdx.z;
    const int i0 = blockIdx.y * 32;
    const int j0 = blockIdx.x * 32;
    // skip tiles entirely above the causal band (j <= i + M)
    if (j0 > i0 + 31 + MM_) return;

    __shared__ __align__(16) float Qs[32][68];
    __shared__ __align__(16) float Ks[32][68];
    __shared__ float Ppre[H_ * H_];

    const int tid = threadIdx.x;
    Ppre[tid] = pre[tid];                         // 256 threads, 256 elems

    const int lr = tid >> 3;                      // 0..31 row
    const int lc = (tid & 7) << 2;                // 0..28 (floats)
    const int tx = tid & 15;
    const int ty = tid >> 4;
    const int ir = ty << 1;
    const int jr = tx << 1;

    float acc[H_][4];
#pragma unroll
    for (int ko = 0; ko < H_; ko++)
#pragma unroll
        for (int e = 0; e < 4; e++) acc[ko][e] = 0.f;

#pragma unroll 1
    for (int h = 0; h < H_; h++) {
        const float* qrow = g_q + (((size_t)(b * H_ + h)) * N_ + i0 + lr) * DH_;
        *(float4*)&Qs[lr][lc]      = *(const float4*)(qrow + lc);
        *(float4*)&Qs[lr][lc + 32] = *(const float4*)(qrow + lc + 32);
        const int jrow = j0 + lr;
        if (jrow < J_) {
            const float* krow = g_k + (((size_t)(b * H_ + h)) * J_ + jrow) * DH_;
            *(float4*)&Ks[lr][lc]      = *(const float4*)(krow + lc);
            *(float4*)&Ks[lr][lc + 32] = *(const float4*)(krow + lc + 32);
        } else {
            float4 z = make_float4(0.f, 0.f, 0.f, 0.f);
            *(float4*)&Ks[lr][lc] = z;
            *(float4*)&Ks[lr][lc + 32] = z;
        }
        __syncthreads();

        float s00 = 0.f, s01 = 0.f, s10 = 0.f, s11 = 0.f;
#pragma unroll
        for (int kk = 0; kk < DH_; kk += 4) {
            const float4 qa = *(const float4*)&Qs[ir][kk];
            const float4 qb = *(const float4*)&Qs[ir + 1][kk];
            const float4 ka = *(const float4*)&Ks[jr][kk];
            const float4 kb = *(const float4*)&Ks[jr + 1][kk];
            s00 += qa.x*ka.x + qa.y*ka.y + qa.z*ka.z + qa.w*ka.w;
            s01 += qa.x*kb.x + qa.y*kb.y + qa.z*kb.z + qa.w*kb.w;
            s10 += qb.x*ka.x + qb.y*ka.y + qb.z*ka.z + qb.w*ka.w;
            s11 += qb.x*kb.x + qb.y*kb.y + qb.z*kb.z + qb.w*kb.w;
        }
        s00 *= SCALE_; s01 *= SCALE_; s10 *= SCALE_; s11 *= SCALE_;
#pragma unroll
        for (int ko = 0; ko < H_; ko++) {
            const float p = Ppre[h * H_ + ko];
            acc[ko][0] += p * s00; acc[ko][1] += p * s01;
            acc[ko][2] += p * s10; acc[ko][3] += p * s11;
        }
        __syncthreads();
    }

    const int gi = i0 + ir;
    const int gj = j0 + jr;
#pragma unroll
    for (int ko = 0; ko < H_; ko++) {
        const size_t base = (((size_t)(b * H_ + ko)) * N_ + gi) * J_ + gj;
        if (gj < J_) {
            g_smix[base]          = acc[ko][0];
            g_smix[base + J_]     = acc[ko][2];
        }
        if (gj + 1 < J_) {
            g_smix[base + 1]      = acc[ko][1];
            g_smix[base + 1 + J_] = acc[ko][3];
        }
    }
}

// ---------------- per-row top-k threshold + softmax + sparse A*V -----------------
__device__ __forceinline__ unsigned fkey(float f)
{
    unsigned u = __float_as_uint(f);
    return (u & 0x80000000u) ? ~u : (u | 0x80000000u);
}

__global__ void __launch_bounds__(256) k_topk_av()
{
    const int i  = blockIdx.x;
    const int ko = blockIdx.y;
    const int b  = blockIdx.z;
    const int tid = threadIdx.x;
    const int jmax = min(J_, i + MM_ + 1);

    __shared__ float svals[J_];
    __shared__ int   sidx[J_];
    __shared__ float swgt[J_];
    __shared__ float reds[8];
    __shared__ int   redi[8];
    __shared__ float s_f;
    __shared__ int   s_i;
    __shared__ int   s_cnt;
    __shared__ float accb[4][64];

    const float* row = g_smix + (((size_t)(b * H_ + ko)) * N_ + i) * J_;

    // load row + block max
    float lmax = -3.4e38f;
    for (int j = tid; j < jmax; j += 256) {
        float v = row[j];
        svals[j] = v;
        lmax = fmaxf(lmax, v);
    }
#pragma unroll
    for (int o = 16; o > 0; o >>= 1) lmax = fmaxf(lmax, __shfl_xor_sync(0xffffffffu, lmax, o));
    if ((tid & 31) == 0) reds[tid >> 5] = lmax;
    __syncthreads();
    if (tid == 0) {
        float m = reds[0];
#pragma unroll
        for (int w = 1; w < 8; w++) m = fmaxf(m, reds[w]);
        s_f = m;
    }
    __syncthreads();
    const float vmax = s_f;

    // K-th largest via greedy bit descent on monotone uint keys
    unsigned ans = 0u;
    if (jmax > KTOP_) {
#pragma unroll 1
        for (int bit = 31; bit >= 0; --bit) {
            const unsigned trial = ans | (1u << bit);
            int c = 0;
            for (int j = tid; j < jmax; j += 256)
                c += (fkey(svals[j]) >= trial);
#pragma unroll
            for (int o = 16; o > 0; o >>= 1) c += __shfl_xor_sync(0xffffffffu, c, o);
            if ((tid & 31) == 0) redi[tid >> 5] = c;
            __syncthreads();
            if (tid == 0) {
                int t = 0;
#pragma unroll
                for (int w = 0; w < 8; w++) t += redi[w];
                s_i = t;
            }
            __syncthreads();
            if (s_i >= KTOP_) ans = trial;
        }
    }
    const unsigned tkey = ans;

    // compact survivors + deterministic exp-sum
    if (tid == 0) s_cnt = 0;
    __syncthreads();
    float lsum = 0.f;
    for (int j = tid; j < jmax; j += 256) {
        const float v = svals[j];
        if (fkey(v) >= tkey) {
            const float w = expf(v - vmax);
            lsum += w;
            const int p = atomicAdd(&s_cnt, 1);
            sidx[p] = j;
            swgt[p] = w;
        }
    }
#pragma unroll
    for (int o = 16; o > 0; o >>= 1) lsum += __shfl_xor_sync(0xffffffffu, lsum, o);
    if ((tid & 31) == 0) reds[tid >> 5] = lsum;
    __syncthreads();
    if (tid == 0) {
        float t = 0.f;
#pragma unroll
        for (int w = 0; w < 8; w++) t += reds[w];
        s_f = t;
    }
    __syncthreads();
    const float sumexp = s_f;
    const int nsurv = s_cnt;

    // gather-weighted sum over surviving v rows (~64 rows)
    const int d = tid & 63;
    const int g = tid >> 6;
    float acc = 0.f;
    const float* vb = g_v + ((size_t)(b * H_ + ko)) * J_ * DH_ + d;
    for (int s = g; s < nsurv; s += 4)
        acc += swgt[s] * vb[(size_t)sidx[s] * DH_];
    accb[g][d] = acc;
    __syncthreads();
    if (g == 0) {
        const float tot = accb[0][d] + accb[1][d] + accb[2][d] + accb[3][d];
        g_att[((size_t)(b * N_ + i)) * DIM_ + ko * DH_ + d] = tot / sumexp;
    }
}

// ---------------- launch ---------------------------------------------------------
extern "C" void kernel_launch(void* const* d_in, const int* in_sizes, int n_in,
                              void* d_out, int out_size)
{
    (void)in_sizes; (void)n_in; (void)out_size;
    const float* x    = (const float*)d_in[0];
    const float* Wq   = (const float*)d_in[1];
    const float* Wkv  = (const float*)d_in[2];
    const float* Wo   = (const float*)d_in[3];
    const float* bo   = (const float*)d_in[4];
    const float* pre  = (const float*)d_in[5];
    // d_in[6] = post_proj (unused by reference)
    const float* memk = (const float*)d_in[7];
    const float* memv = (const float*)d_in[8];
    float* out = (float*)d_out;

    k_gemm_q <<<dim3(DIM_ / 64,   (B_ * N_) / 64), 256>>>(x, Wq);
    k_gemm_kv<<<dim3(2*DIM_ / 64, (B_ * N_) / 64), 256>>>(x, Wkv);
    k_scatter_q <<<(B_ * N_ * DIM_) / 256, 256>>>();
    k_scatter_kv<<<(B_ * N_ * 2 * DIM_) / 256, 256>>>();
    k_fill_mem<<<(B_ * H_ * MM_ * DH_) / 256, 256>>>(memk, memv);
    k_dots_mix<<<dim3((J_ + 31) / 32, N_ / 32, B_), 256>>>(pre);
    k_topk_av<<<dim3(N_, H_, B_), 256>>>();
    k_gemm_o<<<dim3(DIM_ / 64, (B_ * N_) / 64), 256>>>(Wo, bo, out);
}

// round 5
// speedup vs baseline: 1.4916x; 1.4916x over previous
#include <cuda_runtime.h>
#include <cstdint>
#include <cstddef>

#define B_    2
#define N_    2048
#define DIM_  1024
#define H_    16
#define DH_   64
#define MM_   16
#define J_    2064          // N_ + MM_
#define KTOP_ 64
#define SCALE_ 0.125f

// ---------------- static device scratch ----------------
__device__ float g_q   [(size_t)B_*H_*N_*DH_];      // (b,h,i,d)
__device__ float g_k   [(size_t)B_*H_*J_*DH_];      // (b,h,j,d), j<M = mem
__device__ float g_v   [(size_t)B_*H_*J_*DH_];
__device__ float g_smix[(size_t)B_*H_*N_*J_];       // mixed scores (b,k,i,j)
__device__ float g_att [(size_t)B_*N_*DIM_];        // attention output (b,i,k*64+d)

// =============== 128x128 / BK=8 / 8x8 SGEMM with fused scatter epilogue ==========
// MODE 0: C = g_att@B + bias (A param ignored; g_att resolved in device code)
// MODE 1: scatter to g_q   (m=b*2048+i, n=h*64+d)
// MODE 2: scatter to g_k/g_v at row M+i
template<int MODE>
__global__ void __launch_bounds__(256) k_gemm(const float* __restrict__ A,
                                              const float* __restrict__ Bm,
                                              const float* __restrict__ bias,
                                              float* __restrict__ C,
                                              int Ndim, int Kdim)
{
    __shared__ __align__(16) float As[8][132];   // transposed, padded
    __shared__ __align__(16) float Bs[8][128];

    const float* Aeff = (MODE == 0) ? g_att : A;   // device-side symbol resolution

    const int tid = threadIdx.x;
    const int tx  = tid & 15;         // n quad index
    const int ty  = tid >> 4;         // m quad index
    const int m0  = blockIdx.y * 128;
    const int n0  = blockIdx.x * 128;

    const int arow = tid >> 1;            // 0..127
    const int acol = (tid & 1) << 2;      // 0 or 4
    const int brow = tid >> 5;            // 0..7
    const int bcol = (tid & 31) << 2;     // 0..124

    float acc[8][8];
#pragma unroll
    for (int r = 0; r < 8; r++)
#pragma unroll
        for (int c = 0; c < 8; c++) acc[r][c] = 0.f;

    const float* aptr = Aeff + (size_t)(m0 + arow) * Kdim + acol;
    const float* bptr = Bm + (size_t)brow * Ndim + n0 + bcol;

    for (int k0 = 0; k0 < Kdim; k0 += 8) {
        const float4 a = *(const float4*)(aptr + k0);
        As[acol + 0][arow] = a.x; As[acol + 1][arow] = a.y;
        As[acol + 2][arow] = a.z; As[acol + 3][arow] = a.w;
        *(float4*)&Bs[brow][bcol] = *(const float4*)(bptr + (size_t)k0 * Ndim);
        __syncthreads();
#pragma unroll
        for (int k = 0; k < 8; k++) {
            const float4 a0 = *(const float4*)&As[k][ty << 2];
            const float4 a1 = *(const float4*)&As[k][(ty << 2) + 64];
            const float4 b0 = *(const float4*)&Bs[k][tx << 2];
            const float4 b1 = *(const float4*)&Bs[k][(tx << 2) + 64];
            const float ar[8] = {a0.x, a0.y, a0.z, a0.w, a1.x, a1.y, a1.z, a1.w};
            const float br[8] = {b0.x, b0.y, b0.z, b0.w, b1.x, b1.y, b1.z, b1.w};
#pragma unroll
            for (int r = 0; r < 8; r++)
#pragma unroll
                for (int c = 0; c < 8; c++)
                    acc[r][c] += ar[r] * br[c];
        }
        __syncthreads();
    }

#pragma unroll
    for (int mq = 0; mq < 2; mq++) {
#pragma unroll
        for (int r = 0; r < 4; r++) {
            const int m = m0 + mq * 64 + (ty << 2) + r;
            const int b = m >> 11;
            const int i = m & (N_ - 1);
#pragma unroll
            for (int nq = 0; nq < 2; nq++) {
                const int n = n0 + nq * 64 + (tx << 2);
                float4 o = make_float4(acc[mq * 4 + r][nq * 4 + 0],
                                       acc[mq * 4 + r][nq * 4 + 1],
                                       acc[mq * 4 + r][nq * 4 + 2],
                                       acc[mq * 4 + r][nq * 4 + 3]);
                if (MODE == 0) {
                    const float4 bz = *(const float4*)(bias + n);
                    o.x += bz.x; o.y += bz.y; o.z += bz.z; o.w += bz.w;
                    *(float4*)(C + (size_t)m * Ndim + n) = o;
                } else if (MODE == 1) {
                    const int h = n >> 6, d = n & 63;
                    *(float4*)(g_q + (((size_t)(b * H_ + h)) * N_ + i) * DH_ + d) = o;
                } else {
                    if (n < DIM_) {
                        const int h = n >> 6, d = n & 63;
                        *(float4*)(g_k + (((size_t)(b * H_ + h)) * J_ + MM_ + i) * DH_ + d) = o;
                    } else {
                        const int c = n - DIM_;
                        const int h = c >> 6, d = c & 63;
                        *(float4*)(g_v + (((size_t)(b * H_ + h)) * J_ + MM_ + i) * DH_ + d) = o;
                    }
                }
            }
        }
    }
}

__global__ void k_fill_mem(const float* __restrict__ mk, const float* __restrict__ mv)
{
    int idx = blockIdx.x * blockDim.x + threadIdx.x;      // B*H*M*DH elems
    int d = idx & 63;
    int r = idx >> 6;
    int j  = r % MM_;  r /= MM_;
    int h  = r % H_;
    int b  = r / H_;
    size_t dst = (((size_t)(b * H_ + h)) * J_ + j) * DH_ + d;
    size_t src = ((size_t)h * MM_ + j) * DH_ + d;
    g_k[dst] = mk[src];
    g_v[dst] = mv[src];
}

// ---------------- fused QK^T + head-mix (pre_proj) -------------------------------
__global__ void __launch_bounds__(256) k_dots_mix(const float* __restrict__ pre)
{
    const int b  = blockIdx.z;
    const int i0 = blockIdx.y * 32;
    const int j0 = blockIdx.x * 32;
    if (j0 > i0 + 31 + MM_) return;     // fully above causal band

    __shared__ __align__(16) float Qs[32][68];
    __shared__ __align__(16) float Ks[32][68];
    __shared__ float Ppre[H_ * H_];

    const int tid = threadIdx.x;
    Ppre[tid] = pre[tid];

    const int lr = tid >> 3;
    const int lc = (tid & 7) << 2;
    const int tx = tid & 15;
    const int ty = tid >> 4;
    const int ir = ty << 1;
    const int jr = tx << 1;

    float acc[H_][4];
#pragma unroll
    for (int ko = 0; ko < H_; ko++)
#pragma unroll
        for (int e = 0; e < 4; e++) acc[ko][e] = 0.f;

#pragma unroll 1
    for (int h = 0; h < H_; h++) {
        const float* qrow = g_q + (((size_t)(b * H_ + h)) * N_ + i0 + lr) * DH_;
        *(float4*)&Qs[lr][lc]      = *(const float4*)(qrow + lc);
        *(float4*)&Qs[lr][lc + 32] = *(const float4*)(qrow + lc + 32);
        const int jrow = j0 + lr;
        if (jrow < J_) {
            const float* krow = g_k + (((size_t)(b * H_ + h)) * J_ + jrow) * DH_;
            *(float4*)&Ks[lr][lc]      = *(const float4*)(krow + lc);
            *(float4*)&Ks[lr][lc + 32] = *(const float4*)(krow + lc + 32);
        } else {
            float4 z = make_float4(0.f, 0.f, 0.f, 0.f);
            *(float4*)&Ks[lr][lc] = z;
            *(float4*)&Ks[lr][lc + 32] = z;
        }
        __syncthreads();

        float s00 = 0.f, s01 = 0.f, s10 = 0.f, s11 = 0.f;
#pragma unroll
        for (int kk = 0; kk < DH_; kk += 4) {
            const float4 qa = *(const float4*)&Qs[ir][kk];
            const float4 qb = *(const float4*)&Qs[ir + 1][kk];
            const float4 ka = *(const float4*)&Ks[jr][kk];
            const float4 kb = *(const float4*)&Ks[jr + 1][kk];
            s00 += qa.x*ka.x + qa.y*ka.y + qa.z*ka.z + qa.w*ka.w;
            s01 += qa.x*kb.x + qa.y*kb.y + qa.z*kb.z + qa.w*kb.w;
            s10 += qb.x*ka.x + qb.y*ka.y + qb.z*ka.z + qb.w*ka.w;
            s11 += qb.x*kb.x + qb.y*kb.y + qb.z*kb.z + qb.w*kb.w;
        }
        s00 *= SCALE_; s01 *= SCALE_; s10 *= SCALE_; s11 *= SCALE_;
#pragma unroll
        for (int ko = 0; ko < H_; ko++) {
            const float p = Ppre[h * H_ + ko];
            acc[ko][0] += p * s00; acc[ko][1] += p * s01;
            acc[ko][2] += p * s10; acc[ko][3] += p * s11;
        }
        __syncthreads();
    }

    const int gi = i0 + ir;
    const int gj = j0 + jr;
#pragma unroll
    for (int ko = 0; ko < H_; ko++) {
        const size_t base = (((size_t)(b * H_ + ko)) * N_ + gi) * J_ + gj;
        if (gj < J_) {
            g_smix[base]          = acc[ko][0];
            g_smix[base + J_]     = acc[ko][2];
        }
        if (gj + 1 < J_) {
            g_smix[base + 1]      = acc[ko][1];
            g_smix[base + 1 + J_] = acc[ko][3];
        }
    }
}

// ---------------- per-row radix-select top-k + softmax + sparse A*V --------------
__device__ __forceinline__ unsigned fkey(float f)
{
    unsigned u = __float_as_uint(f);
    return (u & 0x80000000u) ? ~u : (u | 0x80000000u);
}
__device__ __forceinline__ float finv(unsigned k)
{
    return (k & 0x80000000u) ? __uint_as_float(k ^ 0x80000000u)
                             : __uint_as_float(~k);
}

__global__ void __launch_bounds__(256) k_topk_av()
{
    const int i  = blockIdx.x;
    const int ko = blockIdx.y;
    const int b  = blockIdx.z;
    const int tid = threadIdx.x;
    const int jmax = min(J_, i + MM_ + 1);

    __shared__ unsigned skeys[J_];
    __shared__ int   sidx[J_];
    __shared__ float swgt[J_];
    __shared__ int   hist[256];
    __shared__ int   suf[256];
    __shared__ unsigned redk[8];
    __shared__ float redf[8];
    __shared__ unsigned s_maxk;
    __shared__ float s_sum;
    __shared__ int   s_bin, s_above, s_cnt;
    __shared__ float accb[4][64];

    const float* row = g_smix + (((size_t)(b * H_ + ko)) * N_ + i) * J_;

    // --- load sweep: keys, max-key, top-byte histogram --------------------------
    hist[tid] = 0;
    __syncthreads();
    unsigned lmax = 0u;
    for (int j = tid; j < jmax; j += 256) {
        unsigned k = fkey(row[j]);
        skeys[j] = k;
        lmax = max(lmax, k);
        atomicAdd(&hist[k >> 24], 1);
    }
#pragma unroll
    for (int o = 16; o > 0; o >>= 1) lmax = max(lmax, __shfl_xor_sync(0xffffffffu, lmax, o));
    if ((tid & 31) == 0) redk[tid >> 5] = lmax;
    __syncthreads();
    if (tid == 0) {
        unsigned m = redk[0];
#pragma unroll
        for (int w = 1; w < 8; w++) m = max(m, redk[w]);
        s_maxk = m;
    }
    __syncthreads();
    const float vmax = finv(s_maxk);

    // --- 4-pass radix select (8 bits per pass, MSB first) -----------------------
    unsigned tkey = 0u;
    if (jmax > KTOP_) {
        unsigned prefix = 0u;
        int kth = KTOP_;
#pragma unroll 1
        for (int pass = 0; pass < 4; pass++) {
            const int shift = 24 - pass * 8;
            if (pass > 0) {
                hist[tid] = 0;
                __syncthreads();
                for (int j = tid; j < jmax; j += 256) {
                    const unsigned k = skeys[j];
                    if ((k >> (shift + 8)) == prefix)
                        atomicAdd(&hist[(k >> shift) & 255u], 1);
                }
                __syncthreads();
            }
            // suffix sum over 256 bins
            suf[tid] = hist[tid];
            __syncthreads();
#pragma unroll 1
            for (int s = 1; s < 256; s <<= 1) {
                int v = suf[tid];
                if (tid + s < 256) v += suf[tid + s];
                __syncthreads();
                suf[tid] = v;
                __syncthreads();
            }
            const int above = (tid == 255) ? 0 : suf[tid + 1];
            if (suf[tid] >= kth && above < kth) { s_bin = tid; s_above = above; }
            __syncthreads();
            prefix = (prefix << 8) | (unsigned)s_bin;
            kth -= s_above;
            __syncthreads();
        }
        tkey = prefix;
    }

    // --- compact survivors + deterministic exp-sum ------------------------------
    if (tid == 0) s_cnt = 0;
    __syncthreads();
    float lsum = 0.f;
    for (int j = tid; j < jmax; j += 256) {
        const unsigned k = skeys[j];
        if (k >= tkey) {
            const float w = expf(finv(k) - vmax);
            lsum += w;
            const int p = atomicAdd(&s_cnt, 1);
            sidx[p] = j;
            swgt[p] = w;
        }
    }
#pragma unroll
    for (int o = 16; o > 0; o >>= 1) lsum += __shfl_xor_sync(0xffffffffu, lsum, o);
    if ((tid & 31) == 0) redf[tid >> 5] = lsum;
    __syncthreads();
    if (tid == 0) {
        float t = 0.f;
#pragma unroll
        for (int w = 0; w < 8; w++) t += redf[w];
        s_sum = t;
    }
    __syncthreads();
    const float sumexp = s_sum;
    const int nsurv = s_cnt;

    // --- gather-weighted sum over surviving v rows ------------------------------
    const int d = tid & 63;
    const int g = tid >> 6;
    float acc = 0.f;
    const float* vb = g_v + ((size_t)(b * H_ + ko)) * J_ * DH_ + d;
    for (int s = g; s < nsurv; s += 4)
        acc += swgt[s] * vb[(size_t)sidx[s] * DH_];
    accb[g][d] = acc;
    __syncthreads();
    if (g == 0) {
        const float tot = accb[0][d] + accb[1][d] + accb[2][d] + accb[3][d];
        g_att[((size_t)(b * N_ + i)) * DIM_ + ko * DH_ + d] = tot / sumexp;
    }
}

// ---------------- launch ---------------------------------------------------------
extern "C" void kernel_launch(void* const* d_in, const int* in_sizes, int n_in,
                              void* d_out, int out_size)
{
    (void)in_sizes; (void)n_in; (void)out_size;
    const float* x    = (const float*)d_in[0];
    const float* Wq   = (const float*)d_in[1];
    const float* Wkv  = (const float*)d_in[2];
    const float* Wo   = (const float*)d_in[3];
    const float* bo   = (const float*)d_in[4];
    const float* pre  = (const float*)d_in[5];
    const float* memk = (const float*)d_in[7];
    const float* memv = (const float*)d_in[8];
    float* out = (float*)d_out;

    k_gemm<1><<<dim3(DIM_ / 128,     (B_ * N_) / 128), 256>>>(x, Wq, nullptr, nullptr, DIM_, DIM_);
    k_gemm<2><<<dim3(2 * DIM_ / 128, (B_ * N_) / 128), 256>>>(x, Wkv, nullptr, nullptr, 2 * DIM_, DIM_);
    k_fill_mem<<<(B_ * H_ * MM_ * DH_) / 256, 256>>>(memk, memv);
    k_dots_mix<<<dim3((J_ + 31) / 32, N_ / 32, B_), 256>>>(pre);
    k_topk_av<<<dim3(N_, H_, B_), 256>>>();
    // MODE 0 reads g_att internally (device-side symbol); A arg is a dummy.
    k_gemm<0><<<dim3(DIM_ / 128, (B_ * N_) / 128), 256>>>(nullptr, Wo, bo, out, DIM_, DIM_);
}

// round 6
// speedup vs baseline: 1.7015x; 1.1407x over previous
#include <cuda_runtime.h>
#include <cstdint>
#include <cstddef>

#define B_    2
#define N_    2048
#define DIM_  1024
#define H_    16
#define DH_   64
#define MM_   16
#define J_    2064          // N_ + MM_
#define KTOP_ 64
#define SCALE_ 0.125f

// ---------------- static device scratch ----------------
__device__ float g_q   [(size_t)B_*H_*N_*DH_];      // (b,h,i,d)
__device__ float g_k   [(size_t)B_*H_*J_*DH_];      // (b,h,j,d), j<M = mem
__device__ float g_v   [(size_t)B_*H_*J_*DH_];
__device__ float g_smix[(size_t)B_*H_*N_*J_];       // mixed scores (b,k,i,j)
__device__ float g_att [(size_t)B_*N_*DIM_];        // attention output (b,i,k*64+d)

// =============== 128x128 / BK=8 / 8x8 SGEMM with fused scatter epilogue ==========
// MODE 0: C = g_att@B + bias (A param ignored; g_att resolved in device code)
// MODE 1: scatter to g_q   (m=b*2048+i, n=h*64+d)
// MODE 2: scatter to g_k/g_v at row M+i
template<int MODE>
__global__ void __launch_bounds__(256) k_gemm(const float* __restrict__ A,
                                              const float* __restrict__ Bm,
                                              const float* __restrict__ bias,
                                              float* __restrict__ C,
                                              int Ndim, int Kdim)
{
    __shared__ __align__(16) float As[8][132];   // transposed, padded
    __shared__ __align__(16) float Bs[8][128];

    const float* Aeff = (MODE == 0) ? g_att : A;   // device-side symbol resolution

    const int tid = threadIdx.x;
    const int tx  = tid & 15;         // n quad index
    const int ty  = tid >> 4;         // m quad index
    const int m0  = blockIdx.y * 128;
    const int n0  = blockIdx.x * 128;

    const int arow = tid >> 1;            // 0..127
    const int acol = (tid & 1) << 2;      // 0 or 4
    const int brow = tid >> 5;            // 0..7
    const int bcol = (tid & 31) << 2;     // 0..124

    float acc[8][8];
#pragma unroll
    for (int r = 0; r < 8; r++)
#pragma unroll
        for (int c = 0; c < 8; c++) acc[r][c] = 0.f;

    const float* aptr = Aeff + (size_t)(m0 + arow) * Kdim + acol;
    const float* bptr = Bm + (size_t)brow * Ndim + n0 + bcol;

    for (int k0 = 0; k0 < Kdim; k0 += 8) {
        const float4 a = *(const float4*)(aptr + k0);
        As[acol + 0][arow] = a.x; As[acol + 1][arow] = a.y;
        As[acol + 2][arow] = a.z; As[acol + 3][arow] = a.w;
        *(float4*)&Bs[brow][bcol] = *(const float4*)(bptr + (size_t)k0 * Ndim);
        __syncthreads();
#pragma unroll
        for (int k = 0; k < 8; k++) {
            const float4 a0 = *(const float4*)&As[k][ty << 2];
            const float4 a1 = *(const float4*)&As[k][(ty << 2) + 64];
            const float4 b0 = *(const float4*)&Bs[k][tx << 2];
            const float4 b1 = *(const float4*)&Bs[k][(tx << 2) + 64];
            const float ar[8] = {a0.x, a0.y, a0.z, a0.w, a1.x, a1.y, a1.z, a1.w};
            const float br[8] = {b0.x, b0.y, b0.z, b0.w, b1.x, b1.y, b1.z, b1.w};
#pragma unroll
            for (int r = 0; r < 8; r++)
#pragma unroll
                for (int c = 0; c < 8; c++)
                    acc[r][c] += ar[r] * br[c];
        }
        __syncthreads();
    }

#pragma unroll
    for (int mq = 0; mq < 2; mq++) {
#pragma unroll
        for (int r = 0; r < 4; r++) {
            const int m = m0 + mq * 64 + (ty << 2) + r;
            const int b = m >> 11;
            const int i = m & (N_ - 1);
#pragma unroll
            for (int nq = 0; nq < 2; nq++) {
                const int n = n0 + nq * 64 + (tx << 2);
                float4 o = make_float4(acc[mq * 4 + r][nq * 4 + 0],
                                       acc[mq * 4 + r][nq * 4 + 1],
                                       acc[mq * 4 + r][nq * 4 + 2],
                                       acc[mq * 4 + r][nq * 4 + 3]);
                if (MODE == 0) {
                    const float4 bz = *(const float4*)(bias + n);
                    o.x += bz.x; o.y += bz.y; o.z += bz.z; o.w += bz.w;
                    *(float4*)(C + (size_t)m * Ndim + n) = o;
                } else if (MODE == 1) {
                    const int h = n >> 6, d = n & 63;
                    *(float4*)(g_q + (((size_t)(b * H_ + h)) * N_ + i) * DH_ + d) = o;
                } else {
                    if (n < DIM_) {
                        const int h = n >> 6, d = n & 63;
                        *(float4*)(g_k + (((size_t)(b * H_ + h)) * J_ + MM_ + i) * DH_ + d) = o;
                    } else {
                        const int c = n - DIM_;
                        const int h = c >> 6, d = c & 63;
                        *(float4*)(g_v + (((size_t)(b * H_ + h)) * J_ + MM_ + i) * DH_ + d) = o;
                    }
                }
            }
        }
    }
}

__global__ void k_fill_mem(const float* __restrict__ mk, const float* __restrict__ mv)
{
    int idx = blockIdx.x * blockDim.x + threadIdx.x;      // B*H*M*DH elems
    int d = idx & 63;
    int r = idx >> 6;
    int j  = r % MM_;  r /= MM_;
    int h  = r % H_;
    int b  = r / H_;
    size_t dst = (((size_t)(b * H_ + h)) * J_ + j) * DH_ + d;
    size_t src = ((size_t)h * MM_ + j) * DH_ + d;
    g_k[dst] = mk[src];
    g_v[dst] = mv[src];
}

// ---------------- tf32 MMA helpers -----------------------------------------------
__device__ __forceinline__ unsigned to_tf32(float x)
{
    unsigned r;
    asm("cvt.rna.tf32.f32 %0, %1;" : "=r"(r) : "f"(x));
    return r;
}

__device__ __forceinline__ void mma_tf32(float& d0, float& d1, float& d2, float& d3,
                                         unsigned a0, unsigned a1, unsigned a2, unsigned a3,
                                         unsigned b0, unsigned b1)
{
    asm volatile("mma.sync.aligned.m16n8k8.row.col.f32.tf32.tf32.f32 "
                 "{%0,%1,%2,%3}, {%4,%5,%6,%7}, {%8,%9}, {%0,%1,%2,%3};\n"
                 : "+f"(d0), "+f"(d1), "+f"(d2), "+f"(d3)
                 : "r"(a0), "r"(a1), "r"(a2), "r"(a3), "r"(b0), "r"(b1));
}

// ---------------- fused QK^T + head-mix via tf32x3 tensor-core MMA ---------------
// CTA tile: 32(i) x 32(j). 8 warps: warp = (wj<<1)|wi, each owns a 16x8 sub-tile.
// Per head: raw S = Q K^T via mma.m16n8k8 (hi/lo split for fp32-accurate results),
// then mixed into 16 output-head accumulators (4 per thread each).
__global__ void __launch_bounds__(256) k_dots_mix(const float* __restrict__ pre)
{
    const int b  = blockIdx.z;
    const int i0 = blockIdx.y * 32;
    const int j0 = blockIdx.x * 32;
    if (j0 > i0 + 31 + MM_) return;     // fully above causal band

    __shared__ __align__(16) float Qs[32][68];
    __shared__ __align__(16) float Ks[32][68];
    __shared__ float Ppre[H_ * H_];

    const int tid  = threadIdx.x;
    const int warp = tid >> 5;
    const int lane = tid & 31;
    const int wi   = warp & 1;          // i half (0..1)
    const int wj   = warp >> 1;         // j eighth (0..3)
    const int grp  = lane >> 2;         // 0..7
    const int tig  = lane & 3;          // 0..3

    Ppre[tid] = pre[tid];

    const int lr = tid >> 3;            // 0..31 row for tile loads
    const int lc = (tid & 7) << 2;      // 0..28

    const int ri = wi * 16 + grp;       // A-frag row in tile
    const int rj = wj * 8 + grp;        // B-frag row (j) in tile

    float acc[H_][4];
#pragma unroll
    for (int ko = 0; ko < H_; ko++)
#pragma unroll
        for (int e = 0; e < 4; e++) acc[ko][e] = 0.f;

#pragma unroll 1
    for (int h = 0; h < H_; h++) {
        const float* qrow = g_q + (((size_t)(b * H_ + h)) * N_ + i0 + lr) * DH_;
        *(float4*)&Qs[lr][lc]      = *(const float4*)(qrow + lc);
        *(float4*)&Qs[lr][lc + 32] = *(const float4*)(qrow + lc + 32);
        const int jrow = j0 + lr;
        if (jrow < J_) {
            const float* krow = g_k + (((size_t)(b * H_ + h)) * J_ + jrow) * DH_;
            *(float4*)&Ks[lr][lc]      = *(const float4*)(krow + lc);
            *(float4*)&Ks[lr][lc + 32] = *(const float4*)(krow + lc + 32);
        } else {
            float4 z = make_float4(0.f, 0.f, 0.f, 0.f);
            *(float4*)&Ks[lr][lc] = z;
            *(float4*)&Ks[lr][lc + 32] = z;
        }
        __syncthreads();

        float s0 = 0.f, s1 = 0.f, s2 = 0.f, s3 = 0.f;
#pragma unroll
        for (int k0 = 0; k0 < DH_; k0 += 8) {
            const float a0f = Qs[ri]    [k0 + tig];
            const float a1f = Qs[ri + 8][k0 + tig];
            const float a2f = Qs[ri]    [k0 + tig + 4];
            const float a3f = Qs[ri + 8][k0 + tig + 4];
            const float b0f = Ks[rj][k0 + tig];
            const float b1f = Ks[rj][k0 + tig + 4];

            const unsigned a0h = to_tf32(a0f), a1h = to_tf32(a1f);
            const unsigned a2h = to_tf32(a2f), a3h = to_tf32(a3f);
            const unsigned b0h = to_tf32(b0f), b1h = to_tf32(b1f);
            const unsigned a0l = to_tf32(a0f - __uint_as_float(a0h));
            const unsigned a1l = to_tf32(a1f - __uint_as_float(a1h));
            const unsigned a2l = to_tf32(a2f - __uint_as_float(a2h));
            const unsigned a3l = to_tf32(a3f - __uint_as_float(a3h));
            const unsigned b0l = to_tf32(b0f - __uint_as_float(b0h));
            const unsigned b1l = to_tf32(b1f - __uint_as_float(b1h));

            mma_tf32(s0, s1, s2, s3, a0h, a1h, a2h, a3h, b0h, b1h);   // hi*hi
            mma_tf32(s0, s1, s2, s3, a0l, a1l, a2l, a3l, b0h, b1h);   // lo*hi
            mma_tf32(s0, s1, s2, s3, a0h, a1h, a2h, a3h, b0l, b1l);   // hi*lo
        }

#pragma unroll
        for (int ko = 0; ko < H_; ko++) {
            const float p = Ppre[h * H_ + ko] * SCALE_;
            acc[ko][0] += p * s0; acc[ko][1] += p * s1;
            acc[ko][2] += p * s2; acc[ko][3] += p * s3;
        }
        __syncthreads();
    }

    // epilogue: D-fragment mapping (rows gi, gi+8; cols gj, gj+1)
    const int gi = i0 + ri;
    const int gj = j0 + wj * 8 + tig * 2;
#pragma unroll
    for (int ko = 0; ko < H_; ko++) {
        const size_t base = (((size_t)(b * H_ + ko)) * N_ + gi) * J_ + gj;
        if (gj < J_) {
            g_smix[base]              = acc[ko][0];
            g_smix[base + 8 * J_]     = acc[ko][2];
        }
        if (gj + 1 < J_) {
            g_smix[base + 1]          = acc[ko][1];
            g_smix[base + 8 * J_ + 1] = acc[ko][3];
        }
    }
}

// ---------------- per-row radix-select top-k + softmax + sparse A*V --------------
__device__ __forceinline__ unsigned fkey(float f)
{
    unsigned u = __float_as_uint(f);
    return (u & 0x80000000u) ? ~u : (u | 0x80000000u);
}
__device__ __forceinline__ float finv(unsigned k)
{
    return (k & 0x80000000u) ? __uint_as_float(k ^ 0x80000000u)
                             : __uint_as_float(~k);
}

__global__ void __launch_bounds__(256) k_topk_av()
{
    const int i  = blockIdx.x;
    const int ko = blockIdx.y;
    const int b  = blockIdx.z;
    const int tid = threadIdx.x;
    const int jmax = min(J_, i + MM_ + 1);

    __shared__ unsigned skeys[J_];
    __shared__ int   sidx[J_];
    __shared__ float swgt[J_];
    __shared__ int   hist[256];
    __shared__ int   suf[256];
    __shared__ unsigned redk[8];
    __shared__ float redf[8];
    __shared__ unsigned s_maxk;
    __shared__ float s_sum;
    __shared__ int   s_bin, s_above, s_cnt;
    __shared__ float accb[4][64];

    const float* row = g_smix + (((size_t)(b * H_ + ko)) * N_ + i) * J_;

    // --- load sweep: keys, max-key, top-byte histogram --------------------------
    hist[tid] = 0;
    __syncthreads();
    unsigned lmax = 0u;
    for (int j = tid; j < jmax; j += 256) {
        unsigned k = fkey(row[j]);
        skeys[j] = k;
        lmax = max(lmax, k);
        atomicAdd(&hist[k >> 24], 1);
    }
#pragma unroll
    for (int o = 16; o > 0; o >>= 1) lmax = max(lmax, __shfl_xor_sync(0xffffffffu, lmax, o));
    if ((tid & 31) == 0) redk[tid >> 5] = lmax;
    __syncthreads();
    if (tid == 0) {
        unsigned m = redk[0];
#pragma unroll
        for (int w = 1; w < 8; w++) m = max(m, redk[w]);
        s_maxk = m;
    }
    __syncthreads();
    const float vmax = finv(s_maxk);

    // --- 4-pass radix select (8 bits per pass, MSB first) -----------------------
    unsigned tkey = 0u;
    if (jmax > KTOP_) {
        unsigned prefix = 0u;
        int kth = KTOP_;
#pragma unroll 1
        for (int pass = 0; pass < 4; pass++) {
            const int shift = 24 - pass * 8;
            if (pass > 0) {
                hist[tid] = 0;
                __syncthreads();
                for (int j = tid; j < jmax; j += 256) {
                    const unsigned k = skeys[j];
                    if ((k >> (shift + 8)) == prefix)
                        atomicAdd(&hist[(k >> shift) & 255u], 1);
                }
                __syncthreads();
            }
            // suffix sum over 256 bins
            suf[tid] = hist[tid];
            __syncthreads();
#pragma unroll 1
            for (int s = 1; s < 256; s <<= 1) {
                int v = suf[tid];
                if (tid + s < 256) v += suf[tid + s];
                __syncthreads();
                suf[tid] = v;
                __syncthreads();
            }
            const int above = (tid == 255) ? 0 : suf[tid + 1];
            if (suf[tid] >= kth && above < kth) { s_bin = tid; s_above = above; }
            __syncthreads();
            prefix = (prefix << 8) | (unsigned)s_bin;
            kth -= s_above;
            __syncthreads();
        }
        tkey = prefix;
    }

    // --- compact survivors + deterministic exp-sum ------------------------------
    if (tid == 0) s_cnt = 0;
    __syncthreads();
    float lsum = 0.f;
    for (int j = tid; j < jmax; j += 256) {
        const unsigned k = skeys[j];
        if (k >= tkey) {
            const float w = expf(finv(k) - vmax);
            lsum += w;
            const int p = atomicAdd(&s_cnt, 1);
            sidx[p] = j;
            swgt[p] = w;
        }
    }
#pragma unroll
    for (int o = 16; o > 0; o >>= 1) lsum += __shfl_xor_sync(0xffffffffu, lsum, o);
    if ((tid & 31) == 0) redf[tid >> 5] = lsum;
    __syncthreads();
    if (tid == 0) {
        float t = 0.f;
#pragma unroll
        for (int w = 0; w < 8; w++) t += redf[w];
        s_sum = t;
    }
    __syncthreads();
    const float sumexp = s_sum;
    const int nsurv = s_cnt;

    // --- gather-weighted sum over surviving v rows ------------------------------
    const int d = tid & 63;
    const int g = tid >> 6;
    float acc = 0.f;
    const float* vb = g_v + ((size_t)(b * H_ + ko)) * J_ * DH_ + d;
    for (int s = g; s < nsurv; s += 4)
        acc += swgt[s] * vb[(size_t)sidx[s] * DH_];
    accb[g][d] = acc;
    __syncthreads();
    if (g == 0) {
        const float tot = accb[0][d] + accb[1][d] + accb[2][d] + accb[3][d];
        g_att[((size_t)(b * N_ + i)) * DIM_ + ko * DH_ + d] = tot / sumexp;
    }
}

// ---------------- launch ---------------------------------------------------------
extern "C" void kernel_launch(void* const* d_in, const int* in_sizes, int n_in,
                              void* d_out, int out_size)
{
    (void)in_sizes; (void)n_in; (void)out_size;
    const float* x    = (const float*)d_in[0];
    const float* Wq   = (const float*)d_in[1];
    const float* Wkv  = (const float*)d_in[2];
    const float* Wo   = (const float*)d_in[3];
    const float* bo   = (const float*)d_in[4];
    const float* pre  = (const float*)d_in[5];
    const float* memk = (const float*)d_in[7];
    const float* memv = (const float*)d_in[8];
    float* out = (float*)d_out;

    k_gemm<1><<<dim3(DIM_ / 128,     (B_ * N_) / 128), 256>>>(x, Wq, nullptr, nullptr, DIM_, DIM_);
    k_gemm<2><<<dim3(2 * DIM_ / 128, (B_ * N_) / 128), 256>>>(x, Wkv, nullptr, nullptr, 2 * DIM_, DIM_);
    k_fill_mem<<<(B_ * H_ * MM_ * DH_) / 256, 256>>>(memk, memv);
    k_dots_mix<<<dim3((J_ + 31) / 32, N_ / 32, B_), 256>>>(pre);
    k_topk_av<<<dim3(N_, H_, B_), 256>>>();
    // MODE 0 reads g_att internally (device-side symbol); A arg is a dummy.
    k_gemm<0><<<dim3(DIM_ / 128, (B_ * N_) / 128), 256>>>(nullptr, Wo, bo, out, DIM_, DIM_);
}